// round 3
// baseline (speedup 1.0000x reference)
#include <cuda_runtime.h>

// Problem constants (fixed by reference)
#define NC       10000
#define ND       1000000
#define B        8192
#define K        64
#define EMB      16
#define CH_DENSE 16
#define DEV_DENSE 20
#define H1       64
#define H2       64
#define ATTN_H   84
#define IN1      32      // CH_DENSE + EMB
#define IN2      132     // DEV_DENSE + 7*EMB

// Scratch
__device__ float g_mean[2 * B * IN2];  // masked-mean features  [2B, 132]
__device__ float g_h[2 * B * H2];      // projected aggregates  [2B, 64]

// ---------------------------------------------------------------------------
// Kernel A: per (vertex, side) neighbor gather + masked mean
//   grid = (B, 2), block = 160 threads
//   float4-vectorized gathers, register accumulation, no weight work
// ---------------------------------------------------------------------------
__global__ __launch_bounds__(160)
void agg_mean_kernel(const float* __restrict__ device_dense,   // [ND, 20]
                     const int*   __restrict__ device_cat,     // [ND, 7]
                     const float* __restrict__ lang_emb,
                     const float* __restrict__ plat_emb,
                     const float* __restrict__ os_emb,
                     const float* __restrict__ country_emb,
                     const float* __restrict__ carrier_emb,
                     const float* __restrict__ brand_emb,
                     const float* __restrict__ plat_os_emb,
                     const int*   __restrict__ bot_neibrs,     // [B, K]
                     const int*   __restrict__ normal_neibrs,  // [B, K]
                     const int*   __restrict__ bot_counts,     // [B]
                     const int*   __restrict__ normal_counts)  // [B]
{
    const int b    = blockIdx.x;
    const int side = blockIdx.y;
    const int t    = threadIdx.x;

    __shared__ int    s_nb[K];
    __shared__ int    s_cat[K * 7];
    __shared__ float4 s_dpart[8][5];    // [k-chunk][dense float4 group]
    __shared__ float4 s_epart[4][28];   // [k-chunk][emb float4 group]

    const int* __restrict__ neibrs = side ? normal_neibrs : bot_neibrs;
    const int* __restrict__ counts = side ? normal_counts : bot_counts;

    int cnt = counts[b];
    cnt = cnt < 1 ? 1 : (cnt > K ? K : cnt);

    // Phase 1: neighbor indices
    if (t < K) s_nb[t] = neibrs[b * K + t];
    __syncthreads();

    // Phase 2: gather categorical rows (7 ints each) into smem
    for (int i = t; i < cnt * 7; i += 160) {
        int k = i / 7, j = i - k * 7;
        s_cat[i] = device_cat[(long)s_nb[k] * 7 + j];
    }
    __syncthreads();

    // Phase 3a: dense sum. threads 0..39 : fg in [0,5) (float4 of the 20 cols),
    //           kc in [0,8). Vectorized 16B loads, register accumulate.
    if (t < 40) {
        const int fg = t % 5, kc = t / 5;
        float4 acc = make_float4(0.f, 0.f, 0.f, 0.f);
        for (int k = kc; k < cnt; k += 8) {
            const float4 v = *(const float4*)(device_dense + (long)s_nb[k] * DEV_DENSE + fg * 4);
            acc.x += v.x; acc.y += v.y; acc.z += v.z; acc.w += v.w;
        }
        s_dpart[kc][fg] = acc;
    }
    // Phase 3b: embedding sum. threads 48..159 (112): fg in [0,28) covering
    //           7 tables x 4 float4-groups; kc in [0,4).
    else if (t >= 48) {
        const int u  = t - 48;
        const int fg = u % 28, kc = u / 28;
        const int j  = fg >> 2;            // table id
        const int e4 = (fg & 3) * 4;       // element offset in embedding row
        const float* __restrict__ tab;
        switch (j) {
            case 0: tab = lang_emb;    break;
            case 1: tab = plat_emb;    break;
            case 2: tab = os_emb;      break;
            case 3: tab = country_emb; break;
            case 4: tab = carrier_emb; break;
            case 5: tab = brand_emb;   break;
            default: tab = plat_os_emb; break;
        }
        float4 acc = make_float4(0.f, 0.f, 0.f, 0.f);
        for (int k = kc; k < cnt; k += 4) {
            const int c = s_cat[k * 7 + j];
            const float4 v = *(const float4*)(tab + c * EMB + e4);
            acc.x += v.x; acc.y += v.y; acc.z += v.z; acc.w += v.w;
        }
        s_epart[kc][fg] = acc;
    }
    __syncthreads();

    // Phase 4: reduce partials, divide by count, write mean row
    if (t < IN2) {
        const float inv = 1.f / (float)cnt;
        float s = 0.f;
        if (t < DEV_DENSE) {
            const float* dp = (const float*)s_dpart;
            #pragma unroll
            for (int kc = 0; kc < 8; ++kc) s += dp[kc * 20 + t];
        } else {
            const int f = t - DEV_DENSE;
            const float* ep = (const float*)s_epart;
            #pragma unroll
            for (int kc = 0; kc < 4; ++kc) s += ep[kc * 112 + f];
        }
        g_mean[(long)(side * B + b) * IN2 + t] = s * inv;
    }
}

// ---------------------------------------------------------------------------
// Kernel B: h = mean @ W_agg + b_agg, weights register-cached per block
//   grid = 256 blocks, 256 threads; each block streams 64 rows (2 per iter)
//   thread role: c = t&63 (output col), ch = t>>6 (one of 4 chunks of 33 i's)
// ---------------------------------------------------------------------------
__global__ __launch_bounds__(256)
void proj_kernel(const float* __restrict__ W_agg,   // [132, 64]
                 const float* __restrict__ b_agg)   // [64]
{
    const int t  = threadIdx.x;
    const int c  = t & 63;
    const int ch = t >> 6;

    __shared__ float s_x[2][IN2];
    __shared__ float s_p[4][2][64];

    float w[33];
    #pragma unroll
    for (int ii = 0; ii < 33; ++ii)
        w[ii] = W_agg[(ch * 33 + ii) * H2 + c];
    const float bias = (t < 128) ? b_agg[c] : 0.f;

    const int r0base = blockIdx.x * 64;
    for (int it = 0; it < 32; ++it) {
        const int r0 = r0base + 2 * it;
        // stage two mean rows (strided: 264 elements > 256 threads)
        for (int i = t; i < 2 * IN2; i += 256) {
            const int r  = (i < IN2) ? 0 : 1;
            const int ci = i - r * IN2;
            s_x[r][ci] = g_mean[(long)(r0 + r) * IN2 + ci];
        }
        __syncthreads();

        float p0 = 0.f, p1 = 0.f;
        #pragma unroll
        for (int ii = 0; ii < 33; ++ii) {
            const float wv = w[ii];
            p0 = fmaf(wv, s_x[0][ch * 33 + ii], p0);
            p1 = fmaf(wv, s_x[1][ch * 33 + ii], p1);
        }
        s_p[ch][0][c] = p0;
        s_p[ch][1][c] = p1;
        __syncthreads();

        if (t < 128) {
            const int row = t >> 6;
            const float h = bias + s_p[0][row][c] + s_p[1][row][c]
                                 + s_p[2][row][c] + s_p[3][row][c];
            g_h[(long)(r0 + row) * H2 + c] = h;
        }
        __syncthreads();
    }
}

// ---------------------------------------------------------------------------
// Kernel C: finalize (attention MLP + softmax2 + combine + self linear)
//   grid = 256 blocks, 256 threads, 32 vertices per block
//   W_attn register-cached: t<252 : c = t%84, ch = t/84, 32 weights each
//   W_self register-cached: all t : sc = t&63, sch = t>>6, 8 weights each
// ---------------------------------------------------------------------------
__global__ __launch_bounds__(256)
void finalize_kernel(const float* __restrict__ channel_dense,  // [NC, 16]
                     const float* __restrict__ channel_id_emb, // [NC, 16]
                     const float* __restrict__ W_self,         // [32, 64]
                     const float* __restrict__ b_self,         // [64]
                     const float* __restrict__ W_attn,         // [96, 84]
                     const float* __restrict__ b_attn,         // [84]
                     const float* __restrict__ W_attn2,        // [84, 1]
                     const float* __restrict__ b_attn2,        // [1]
                     const int*   __restrict__ channel_ids,    // [NC]
                     const int*   __restrict__ vertices,       // [B]
                     float*       __restrict__ out)            // [B, 128]
{
    const int t = threadIdx.x;

    // attention roles
    const int ac  = (t < 252) ? (t % 84) : 0;
    const int ach = (t < 252) ? (t / 84) : 0;
    // self roles
    const int sc  = t & 63;
    const int sch = t >> 6;

    __shared__ float s_hb[H2];
    __shared__ float s_hn[H2];
    __shared__ float s_chv[IN1];
    __shared__ float s_ap[2][3][84];   // attention partials [group][chunk][col]
    __shared__ float s_r[2][84];       // relu(hidden)*W2
    __shared__ float s_sp[4][64];      // self-linear partials
    __shared__ float s_sc[2];          // scores

    // register-cached weights
    float wa[32];
    if (t < 252) {
        #pragma unroll
        for (int ii = 0; ii < 32; ++ii)
            wa[ii] = W_attn[(ach * 32 + ii) * ATTN_H + ac];
    }
    float ws[8];
    #pragma unroll
    for (int ii = 0; ii < 8; ++ii)
        ws[ii] = W_self[(sch * 8 + ii) * H1 + sc];

    const float rb2  = b_attn2[0];
    const float rba  = (t < 168) ? b_attn[t % 84]  : 0.f;
    const float rw2  = (t < 168) ? W_attn2[t % 84] : 0.f;
    const float rbs  = (t >= 64 && t < 128) ? b_self[t - 64] : 0.f;

    const int bi0 = blockIdx.x * 32;
    for (int it = 0; it < 32; ++it) {
        const int bi = bi0 + it;
        const int v  = vertices[bi];

        // stage inputs
        if (t < H2)                 s_hb[t]        = g_h[(long)bi * H2 + t];
        else if (t < 2 * H2)        s_hn[t - H2]   = g_h[(long)(B + bi) * H2 + (t - H2)];
        else if (t < 2 * H2 + 16)   s_chv[t - 128] = channel_dense[(long)v * CH_DENSE + (t - 128)];
        else if (t < 2 * H2 + 32) {
            const int cid = channel_ids[v];
            s_chv[t - 128] = channel_id_emb[(long)cid * EMB + (t - 144)];
        }
        __syncthreads();

        // attention partials (both groups) + self partials
        if (t < 252) {
            const float* __restrict__ src0 = (ach < 2) ? (s_hb + ach * 32) : s_chv;
            const float* __restrict__ src1 = (ach < 2) ? (s_hn + ach * 32) : s_chv;
            float p0 = 0.f, p1 = 0.f;
            #pragma unroll
            for (int ii = 0; ii < 32; ++ii) {
                const float wv = wa[ii];
                p0 = fmaf(wv, src0[ii], p0);
                p1 = fmaf(wv, src1[ii], p1);
            }
            s_ap[0][ach][ac] = p0;
            s_ap[1][ach][ac] = p1;
        }
        {
            float ps = 0.f;
            #pragma unroll
            for (int ii = 0; ii < 8; ++ii)
                ps = fmaf(ws[ii], s_chv[sch * 8 + ii], ps);
            s_sp[sch][sc] = ps;
        }
        __syncthreads();

        // hidden reduce + relu + *W2
        if (t < 168) {
            const int g = t / 84, c = t % 84;
            const float h = rba + s_ap[g][0][c] + s_ap[g][1][c] + s_ap[g][2][c];
            s_r[g][c] = fmaxf(h, 0.f) * rw2;
        }
        __syncthreads();

        // score reduce over 84 (one warp per group)
        if (t < 64) {
            const int g = t >> 5, lane = t & 31;
            float s = 0.f;
            for (int c = lane; c < ATTN_H; c += 32) s += s_r[g][c];
            #pragma unroll
            for (int off = 16; off > 0; off >>= 1)
                s += __shfl_down_sync(0xffffffffu, s, off);
            if (lane == 0) s_sc[g] = s + rb2;
        }
        __syncthreads();

        // softmax(2) + outputs
        const float m   = fmaxf(s_sc[0], s_sc[1]);
        const float e0  = __expf(s_sc[0] - m);
        const float e1  = __expf(s_sc[1] - m);
        const float inv = 1.f / (e0 + e1);
        const float a0  = e0 * inv, a1 = e1 * inv;

        if (t < H2) {
            out[(long)bi * (H2 + H1) + t] = fmaxf(a0 * s_hb[t] + a1 * s_hn[t], 0.f);
        } else if (t < H2 + H1) {
            const int c = t - H2;
            const float o = rbs + s_sp[0][c] + s_sp[1][c] + s_sp[2][c] + s_sp[3][c];
            out[(long)bi * (H2 + H1) + t] = fmaxf(o, 0.f);
        }
        __syncthreads();
    }
}

// ---------------------------------------------------------------------------
extern "C" void kernel_launch(void* const* d_in, const int* in_sizes, int n_in,
                              void* d_out, int out_size)
{
    const float* channel_dense  = (const float*)d_in[0];
    const float* device_dense   = (const float*)d_in[1];
    const float* channel_id_emb = (const float*)d_in[2];
    const float* lang_emb       = (const float*)d_in[3];
    const float* plat_emb       = (const float*)d_in[4];
    const float* os_emb         = (const float*)d_in[5];
    const float* country_emb    = (const float*)d_in[6];
    const float* carrier_emb    = (const float*)d_in[7];
    const float* brand_emb      = (const float*)d_in[8];
    const float* plat_os_emb    = (const float*)d_in[9];
    const float* W_agg          = (const float*)d_in[10];
    const float* b_agg          = (const float*)d_in[11];
    const float* W_self         = (const float*)d_in[12];
    const float* b_self         = (const float*)d_in[13];
    const float* W_attn         = (const float*)d_in[14];
    const float* b_attn         = (const float*)d_in[15];
    const float* W_attn2        = (const float*)d_in[16];
    const float* b_attn2        = (const float*)d_in[17];
    const int*   channel_ids    = (const int*)d_in[18];
    const int*   device_cat     = (const int*)d_in[19];
    const int*   vertices       = (const int*)d_in[20];
    const int*   bot_neibrs     = (const int*)d_in[21];
    const int*   normal_neibrs  = (const int*)d_in[22];
    const int*   bot_counts     = (const int*)d_in[23];
    const int*   normal_counts  = (const int*)d_in[24];

    float* out = (float*)d_out;

    dim3 gridA(B, 2);
    agg_mean_kernel<<<gridA, 160>>>(device_dense, device_cat,
                                    lang_emb, plat_emb, os_emb, country_emb,
                                    carrier_emb, brand_emb, plat_os_emb,
                                    bot_neibrs, normal_neibrs,
                                    bot_counts, normal_counts);

    proj_kernel<<<256, 256>>>(W_agg, b_agg);

    finalize_kernel<<<256, 256>>>(channel_dense, channel_id_emb,
                                  W_self, b_self, W_attn, b_attn,
                                  W_attn2, b_attn2,
                                  channel_ids, vertices, out);
}